// round 3
// baseline (speedup 1.0000x reference)
#include <cuda_runtime.h>
#include <cstdint>

// ---------------------------------------------------------------------------
// Problem constants
// ---------------------------------------------------------------------------
#define LQ      4096
#define NB      8
#define CDIM    256
#define MROWS   (LQ * NB)          // 32768
#define NHEADS  8
#define NLEV    4
#define NPTS    4
#define DH      32
#define FMSTRIDE (NB * CDIM)       // 2048 floats per spatial cell row

// ---------------------------------------------------------------------------
// Scratch (__device__ globals; cudaMalloc is forbidden)
// ---------------------------------------------------------------------------
__device__ float g_off[MROWS * 256];
__device__ float g_logits[MROWS * 128];
__device__ float g_agg[MROWS * 256];

// ---------------------------------------------------------------------------
// Double-buffered SGEMM core: 128x128 tile, BK=16, 256 threads, 8x8/thread.
// Ab: A block base (row-major, leading dim K). Bb: B col-offset base (leading
// dim N). Cb: output tile base (leading dim N). biasp: bias for these cols.
// ---------------------------------------------------------------------------
__device__ __forceinline__ void sgemm_core(const float* __restrict__ Ab,
                                           const float* __restrict__ Bb,
                                           const float* __restrict__ biasp,
                                           float* __restrict__ Cb,
                                           int N, int K) {
    __shared__ float As[2][16][128];
    __shared__ float Bs[2][16][128];

    const int tid = threadIdx.x;
    const int tx  = tid & 15;
    const int ty  = tid >> 4;

    // A staging: 128x16 tile = 512 float4, 2 per thread (transposed store)
    const int arow0 = tid >> 2;            // 0..63
    const int acol  = (tid & 3) * 4;       // 0,4,8,12
    // B staging: 16x128 tile = 512 float4, 2 per thread
    const int brow0 = tid >> 5;            // 0..7
    const int bcol  = (tid & 31) * 4;      // 0..124

    float acc[8][8];
#pragma unroll
    for (int i = 0; i < 8; i++)
#pragma unroll
        for (int j = 0; j < 8; j++) acc[i][j] = 0.f;

    const int nk = K / 16;

    // Preload tile 0
    float4 a0 = *(const float4*)(Ab + (size_t)arow0 * K + acol);
    float4 a1 = *(const float4*)(Ab + (size_t)(arow0 + 64) * K + acol);
    float4 b0 = *(const float4*)(Bb + (size_t)brow0 * N + bcol);
    float4 b1 = *(const float4*)(Bb + (size_t)(brow0 + 8) * N + bcol);

    As[0][acol + 0][arow0] = a0.x; As[0][acol + 1][arow0] = a0.y;
    As[0][acol + 2][arow0] = a0.z; As[0][acol + 3][arow0] = a0.w;
    As[0][acol + 0][arow0 + 64] = a1.x; As[0][acol + 1][arow0 + 64] = a1.y;
    As[0][acol + 2][arow0 + 64] = a1.z; As[0][acol + 3][arow0 + 64] = a1.w;
    *(float4*)&Bs[0][brow0][bcol]     = b0;
    *(float4*)&Bs[0][brow0 + 8][bcol] = b1;
    __syncthreads();

    for (int kb = 0; kb < nk; kb++) {
        const int cur = kb & 1;
        const bool more = (kb + 1) < nk;
        if (more) {
            const int k0 = (kb + 1) * 16;
            a0 = *(const float4*)(Ab + (size_t)arow0 * K + k0 + acol);
            a1 = *(const float4*)(Ab + (size_t)(arow0 + 64) * K + k0 + acol);
            b0 = *(const float4*)(Bb + (size_t)(k0 + brow0) * N + bcol);
            b1 = *(const float4*)(Bb + (size_t)(k0 + brow0 + 8) * N + bcol);
        }
#pragma unroll
        for (int kk = 0; kk < 16; kk++) {
            float4 ra0 = *(const float4*)&As[cur][kk][ty * 8 + 0];
            float4 ra1 = *(const float4*)&As[cur][kk][ty * 8 + 4];
            float4 rb0 = *(const float4*)&Bs[cur][kk][tx * 8 + 0];
            float4 rb1 = *(const float4*)&Bs[cur][kk][tx * 8 + 4];
            float ra[8] = {ra0.x, ra0.y, ra0.z, ra0.w, ra1.x, ra1.y, ra1.z, ra1.w};
            float rb[8] = {rb0.x, rb0.y, rb0.z, rb0.w, rb1.x, rb1.y, rb1.z, rb1.w};
#pragma unroll
            for (int i = 0; i < 8; i++)
#pragma unroll
                for (int j = 0; j < 8; j++) acc[i][j] += ra[i] * rb[j];
        }
        if (more) {
            const int nxt = 1 - cur;
            As[nxt][acol + 0][arow0] = a0.x; As[nxt][acol + 1][arow0] = a0.y;
            As[nxt][acol + 2][arow0] = a0.z; As[nxt][acol + 3][arow0] = a0.w;
            As[nxt][acol + 0][arow0 + 64] = a1.x; As[nxt][acol + 1][arow0 + 64] = a1.y;
            As[nxt][acol + 2][arow0 + 64] = a1.z; As[nxt][acol + 3][arow0 + 64] = a1.w;
            *(float4*)&Bs[nxt][brow0][bcol]     = b0;
            *(float4*)&Bs[nxt][brow0 + 8][bcol] = b1;
            __syncthreads();
        }
    }

#pragma unroll
    for (int i = 0; i < 8; i++) {
        float* Crow = Cb + (size_t)(ty * 8 + i) * N + tx * 8;
#pragma unroll
        for (int j = 0; j < 8; j++)
            Crow[j] = acc[i][j] + biasp[tx * 8 + j];
    }
}

// Fused Q-projection: bx in {0,1} -> W_off cols, bx==2 -> W_attn
__global__ __launch_bounds__(256, 2)
void qproj_kernel(const float* __restrict__ Q,
                  const float* __restrict__ Woff, const float* __restrict__ boff,
                  const float* __restrict__ Wattn, const float* __restrict__ battn) {
    const int bx = blockIdx.x, by = blockIdx.y;
    const float* Ab = Q + (size_t)by * 128 * 256;
    if (bx < 2) {
        sgemm_core(Ab, Woff + bx * 128, boff + bx * 128,
                   g_off + (size_t)by * 128 * 256 + bx * 128, 256, 256);
    } else {
        sgemm_core(Ab, Wattn, battn,
                   g_logits + (size_t)by * 128 * 128, 128, 256);
    }
}

// Output projection
__global__ __launch_bounds__(256, 2)
void outproj_kernel(const float* __restrict__ W, const float* __restrict__ bias,
                    float* __restrict__ out) {
    const int bx = blockIdx.x, by = blockIdx.y;
    sgemm_core(g_agg + (size_t)by * 128 * 256, W + bx * 128, bias + bx * 128,
               out + (size_t)by * 128 * 256 + bx * 128, 256, 256);
}

// ---------------------------------------------------------------------------
// Sampling: one block per query row, one warp per head, lane = channel.
// Fused 16-wide softmax + branchless bilinear gather + weighted accumulate.
// ---------------------------------------------------------------------------
__global__ __launch_bounds__(256)
void sample_kernel(const float* __restrict__ refpts,
                   const float* __restrict__ fm) {
    const int r    = blockIdx.x;
    const int h    = threadIdx.x >> 5;
    const int lane = threadIdx.x & 31;
    const int n    = r & (NB - 1);
    const int lq   = r >> 3;

    const float offv  = g_off[r * 256 + h * 32 + lane];
    const float logit = g_logits[r * 128 + h * 16 + (lane & 15)];

    // Softmax over 16 logits (replicated across warp halves)
    float mx = logit;
#pragma unroll
    for (int s = 8; s > 0; s >>= 1)
        mx = fmaxf(mx, __shfl_xor_sync(0xffffffffu, mx, s));
    float ex = __expf(logit - mx);
    float sm = ex;
#pragma unroll
    for (int s = 8; s > 0; s >>= 1)
        sm += __shfl_xor_sync(0xffffffffu, sm, s);
    const float wgt = ex / sm;

    const int starts[4] = {0, 10000, 12500, 13125};
    const int dims[4]   = {100, 50, 25, 13};

    // Hoist the 8 reference coords
    const float* refr = refpts + ((size_t)(n * LQ + lq) * NLEV) * 2;
    float rxs[4], rys[4];
#pragma unroll
    for (int l = 0; l < NLEV; l++) { rxs[l] = refr[l * 2]; rys[l] = refr[l * 2 + 1]; }

    float acc = 0.f;
#pragma unroll
    for (int l = 0; l < NLEV; l++) {
        const int   Wi = dims[l], Hi = dims[l];
        const float Wf = (float)Wi, Hf = (float)Hi;
        const float* base = fm + (size_t)starts[l] * FMSTRIDE
                               + n * CDIM + h * DH + lane;
        const float rx = rxs[l], ry = rys[l];
#pragma unroll
        for (int p = 0; p < NPTS; p++) {
            const int pt = l * 4 + p;
            const float ox  = __shfl_sync(0xffffffffu, offv, 2 * pt);
            const float oy  = __shfl_sync(0xffffffffu, offv, 2 * pt + 1);
            const float apt = __shfl_sync(0xffffffffu, wgt,  pt);

            const float x = (rx + ox / Wf) * Wf - 0.5f;
            const float y = (ry + oy / Hf) * Hf - 0.5f;

            const float x0f = floorf(x), y0f = floorf(y);
            const int   x0 = (int)x0f,  y0 = (int)y0f;
            const float wx = x - x0f,   wy = y - y0f;

            // Clamped indices (always-safe loads) + validity folded into weights
            const int x0c = min(max(x0, 0), Wi - 1);
            const int x1c = min(max(x0 + 1, 0), Wi - 1);
            const int y0c = min(max(y0, 0), Hi - 1);
            const int y1c = min(max(y0 + 1, 0), Hi - 1);
            const float vx0 = (x0 >= 0 && x0 < Wi) ? 1.f : 0.f;
            const float vx1 = (x0 + 1 >= 0 && x0 + 1 < Wi) ? 1.f : 0.f;
            const float vy0 = (y0 >= 0 && y0 < Hi) ? 1.f : 0.f;
            const float vy1 = (y0 + 1 >= 0 && y0 + 1 < Hi) ? 1.f : 0.f;

            const float w00 = (1.f - wx) * (1.f - wy) * vx0 * vy0 * apt;
            const float w01 = wx         * (1.f - wy) * vx1 * vy0 * apt;
            const float w10 = (1.f - wx) * wy         * vx0 * vy1 * apt;
            const float w11 = wx         * wy         * vx1 * vy1 * apt;

            const float v00 = base[(size_t)(y0c * Wi + x0c) * FMSTRIDE];
            const float v01 = base[(size_t)(y0c * Wi + x1c) * FMSTRIDE];
            const float v10 = base[(size_t)(y1c * Wi + x0c) * FMSTRIDE];
            const float v11 = base[(size_t)(y1c * Wi + x1c) * FMSTRIDE];

            acc = fmaf(v00, w00, acc);
            acc = fmaf(v01, w01, acc);
            acc = fmaf(v10, w10, acc);
            acc = fmaf(v11, w11, acc);
        }
    }
    g_agg[r * 256 + h * 32 + lane] = acc;
}

// ---------------------------------------------------------------------------
// Launch
// ---------------------------------------------------------------------------
extern "C" void kernel_launch(void* const* d_in, const int* in_sizes, int n_in,
                              void* d_out, int out_size) {
    const float* query   = (const float*)d_in[0];
    const float* refpts  = (const float*)d_in[1];
    const float* fmaps   = (const float*)d_in[2];
    const float* W_off   = (const float*)d_in[4];
    const float* b_off   = (const float*)d_in[5];
    const float* W_attn  = (const float*)d_in[6];
    const float* b_attn  = (const float*)d_in[7];
    const float* W_out   = (const float*)d_in[8];
    const float* b_out   = (const float*)d_in[9];
    float* out = (float*)d_out;

    qproj_kernel<<<dim3(3, MROWS / 128), 256>>>(query, W_off, b_off, W_attn, b_attn);
    sample_kernel<<<MROWS, 256>>>(refpts, fmaps);
    outproj_kernel<<<dim3(2, MROWS / 128), 256>>>(W_out, b_out, out);
}

// round 4
// speedup vs baseline: 1.4143x; 1.4143x over previous
#include <cuda_runtime.h>
#include <cstdint>

// ---------------------------------------------------------------------------
// Problem constants
// ---------------------------------------------------------------------------
#define LQ      4096
#define NB      8
#define CDIM    256
#define MROWS   (LQ * NB)          // 32768
#define NHEADS  8
#define NLEV    4
#define NPTS    4
#define DH      32
#define FMSTRIDE (NB * CDIM)       // 2048 floats per spatial cell row

// ---------------------------------------------------------------------------
// Scratch (__device__ globals; cudaMalloc forbidden)
// ---------------------------------------------------------------------------
__device__ float g_off[MROWS * 256];
__device__ float g_logits[MROWS * 128];
__device__ float g_agg[MROWS * 256];

// ---------------------------------------------------------------------------
// TF32 helpers
// ---------------------------------------------------------------------------
__device__ __forceinline__ uint32_t f2tf32(float f) {
    uint32_t u;
    asm("cvt.rna.tf32.f32 %0, %1;" : "=r"(u) : "f"(f));
    return u;
}

__device__ __forceinline__ void mma_tf32(float* c, const uint32_t* a, const uint32_t* b) {
    asm volatile(
        "mma.sync.aligned.m16n8k8.row.col.f32.tf32.tf32.f32 "
        "{%0,%1,%2,%3}, {%4,%5,%6,%7}, {%8,%9}, {%0,%1,%2,%3};"
        : "+f"(c[0]), "+f"(c[1]), "+f"(c[2]), "+f"(c[3])
        : "r"(a[0]), "r"(a[1]), "r"(a[2]), "r"(a[3]), "r"(b[0]), "r"(b[1]));
}

// ---------------------------------------------------------------------------
// TF32 MMA GEMM core: 128x128 tile, BK=16, 256 threads (8 warps in 4x2 grid),
// warp tile 32(m) x 64(n) = 2 m-frags x 8 n-frags of m16n8k8.
// A: row-major (ld K=256). B: row-major (ld ldb). C: row-major (ld ldc).
// Smem: As[128][20] (pad: stride 20 == 4 mod 32 -> conflict-free A frags),
//       Bs[16][136]  (pad: stride 136 == 8 mod 32 -> conflict-free B frags).
// ---------------------------------------------------------------------------
__device__ __forceinline__ void mma_gemm_core(const float* __restrict__ Ab,
                                              const float* __restrict__ Bb,
                                              const float* __restrict__ biasp,
                                              float* __restrict__ Cb,
                                              int ldb, int ldc, int K) {
    __shared__ uint32_t As[2][128][20];
    __shared__ uint32_t Bs[2][16][136];

    const int tid  = threadIdx.x;
    const int wid  = tid >> 5;
    const int lane = tid & 31;
    const int gid  = lane >> 2;      // 0..7
    const int tig  = lane & 3;       // 0..3
    const int wm   = (wid & 3) * 32; // warp m offset
    const int wn   = (wid >> 2) * 64;// warp n offset

    // Global->smem staging mappings
    const int arow = tid >> 1;            // 0..127
    const int acol = (tid & 1) * 8;       // 0 or 8 (two float4: acol, acol+4)
    const int brow = tid >> 5;            // 0..7   (two rows: brow, brow+8)
    const int bcol = (tid & 31) * 4;      // 0..124

    float acc[2][8][4];
#pragma unroll
    for (int i = 0; i < 2; i++)
#pragma unroll
        for (int j = 0; j < 8; j++)
#pragma unroll
            for (int v = 0; v < 4; v++) acc[i][j][v] = 0.f;

    const int nk = K / 16;

    float4 a0 = *(const float4*)(Ab + (size_t)arow * K + acol);
    float4 a1 = *(const float4*)(Ab + (size_t)arow * K + acol + 4);
    float4 b0 = *(const float4*)(Bb + (size_t)brow * ldb + bcol);
    float4 b1 = *(const float4*)(Bb + (size_t)(brow + 8) * ldb + bcol);

    {
        uint32_t* ap = &As[0][arow][acol];
        ap[0] = f2tf32(a0.x); ap[1] = f2tf32(a0.y); ap[2] = f2tf32(a0.z); ap[3] = f2tf32(a0.w);
        ap[4] = f2tf32(a1.x); ap[5] = f2tf32(a1.y); ap[6] = f2tf32(a1.z); ap[7] = f2tf32(a1.w);
        uint32_t* bp0 = &Bs[0][brow][bcol];
        bp0[0] = f2tf32(b0.x); bp0[1] = f2tf32(b0.y); bp0[2] = f2tf32(b0.z); bp0[3] = f2tf32(b0.w);
        uint32_t* bp1 = &Bs[0][brow + 8][bcol];
        bp1[0] = f2tf32(b1.x); bp1[1] = f2tf32(b1.y); bp1[2] = f2tf32(b1.z); bp1[3] = f2tf32(b1.w);
    }
    __syncthreads();

    for (int kb = 0; kb < nk; kb++) {
        const int cur = kb & 1;
        const bool more = (kb + 1) < nk;
        if (more) {
            const int k0 = (kb + 1) * 16;
            a0 = *(const float4*)(Ab + (size_t)arow * K + k0 + acol);
            a1 = *(const float4*)(Ab + (size_t)arow * K + k0 + acol + 4);
            b0 = *(const float4*)(Bb + (size_t)(k0 + brow) * ldb + bcol);
            b1 = *(const float4*)(Bb + (size_t)(k0 + brow + 8) * ldb + bcol);
        }

#pragma unroll
        for (int ks = 0; ks < 2; ks++) {
            const int kk = ks * 8;
            uint32_t af[2][4];
#pragma unroll
            for (int mi = 0; mi < 2; mi++) {
                const int r = wm + mi * 16 + gid;
                af[mi][0] = As[cur][r][kk + tig];
                af[mi][1] = As[cur][r + 8][kk + tig];
                af[mi][2] = As[cur][r][kk + tig + 4];
                af[mi][3] = As[cur][r + 8][kk + tig + 4];
            }
            uint32_t bf[8][2];
#pragma unroll
            for (int ni = 0; ni < 8; ni++) {
                const int c = wn + ni * 8 + gid;
                bf[ni][0] = Bs[cur][kk + tig][c];
                bf[ni][1] = Bs[cur][kk + tig + 4][c];
            }
#pragma unroll
            for (int mi = 0; mi < 2; mi++)
#pragma unroll
                for (int ni = 0; ni < 8; ni++)
                    mma_tf32(acc[mi][ni], af[mi], bf[ni]);
        }

        if (more) {
            const int nxt = 1 - cur;
            uint32_t* ap = &As[nxt][arow][acol];
            ap[0] = f2tf32(a0.x); ap[1] = f2tf32(a0.y); ap[2] = f2tf32(a0.z); ap[3] = f2tf32(a0.w);
            ap[4] = f2tf32(a1.x); ap[5] = f2tf32(a1.y); ap[6] = f2tf32(a1.z); ap[7] = f2tf32(a1.w);
            uint32_t* bp0 = &Bs[nxt][brow][bcol];
            bp0[0] = f2tf32(b0.x); bp0[1] = f2tf32(b0.y); bp0[2] = f2tf32(b0.z); bp0[3] = f2tf32(b0.w);
            uint32_t* bp1 = &Bs[nxt][brow + 8][bcol];
            bp1[0] = f2tf32(b1.x); bp1[1] = f2tf32(b1.y); bp1[2] = f2tf32(b1.z); bp1[3] = f2tf32(b1.w);
            __syncthreads();
        }
    }

    // Epilogue: D frag (mi): c0->(r,c) c1->(r,c+1) c2->(r+8,c) c3->(r+8,c+1)
#pragma unroll
    for (int mi = 0; mi < 2; mi++) {
        const int r = wm + mi * 16 + gid;
#pragma unroll
        for (int ni = 0; ni < 8; ni++) {
            const int c = wn + ni * 8 + tig * 2;
            const float bia0 = biasp[c], bia1 = biasp[c + 1];
            float2 lo = make_float2(acc[mi][ni][0] + bia0, acc[mi][ni][1] + bia1);
            float2 hi = make_float2(acc[mi][ni][2] + bia0, acc[mi][ni][3] + bia1);
            *(float2*)(Cb + (size_t)r * ldc + c)       = lo;
            *(float2*)(Cb + (size_t)(r + 8) * ldc + c) = hi;
        }
    }
}

// Fused Q-projection: bx in {0,1} -> W_off col tiles; bx==2 -> W_attn
__global__ __launch_bounds__(256)
void qproj_kernel(const float* __restrict__ Q,
                  const float* __restrict__ Woff, const float* __restrict__ boff,
                  const float* __restrict__ Wattn, const float* __restrict__ battn) {
    const int bx = blockIdx.x, by = blockIdx.y;
    const float* Ab = Q + (size_t)by * 128 * 256;
    if (bx < 2) {
        mma_gemm_core(Ab, Woff + bx * 128, boff + bx * 128,
                      g_off + (size_t)by * 128 * 256 + bx * 128, 256, 256, 256);
    } else {
        mma_gemm_core(Ab, Wattn, battn,
                      g_logits + (size_t)by * 128 * 128, 128, 128, 256);
    }
}

__global__ __launch_bounds__(256)
void outproj_kernel(const float* __restrict__ W, const float* __restrict__ bias,
                    float* __restrict__ out) {
    const int bx = blockIdx.x, by = blockIdx.y;
    mma_gemm_core(g_agg + (size_t)by * 128 * 256, W + bx * 128, bias + bx * 128,
                  out + (size_t)by * 128 * 256 + bx * 128, 256, 256, 256);
}

// ---------------------------------------------------------------------------
// Sampling: one block per query row, one warp per head, lane = channel.
// Fused 16-wide softmax + flat-predicated bilinear taps (OOB loads skipped,
// all 4 taps independent -> full MLP) + dual accumulators.
// ---------------------------------------------------------------------------
__global__ __launch_bounds__(256)
void sample_kernel(const float* __restrict__ refpts,
                   const float* __restrict__ fm) {
    const int r    = blockIdx.x;
    const int h    = threadIdx.x >> 5;
    const int lane = threadIdx.x & 31;
    const int n    = r & (NB - 1);
    const int lq   = r >> 3;

    const float offv  = g_off[r * 256 + h * 32 + lane];
    const float logit = g_logits[r * 128 + h * 16 + (lane & 15)];

    float mx = logit;
#pragma unroll
    for (int s = 8; s > 0; s >>= 1)
        mx = fmaxf(mx, __shfl_xor_sync(0xffffffffu, mx, s));
    float ex = __expf(logit - mx);
    float sm = ex;
#pragma unroll
    for (int s = 8; s > 0; s >>= 1)
        sm += __shfl_xor_sync(0xffffffffu, sm, s);
    const float wgt = ex / sm;

    const int starts[4] = {0, 10000, 12500, 13125};
    const int dims[4]   = {100, 50, 25, 13};

    // Hoist the 8 reference coords (two float4 loads)
    const float4* refv = (const float4*)(refpts + ((size_t)(n * LQ + lq) * NLEV) * 2);
    const float4 rf0 = refv[0], rf1 = refv[1];
    const float rxs[4] = {rf0.x, rf0.z, rf1.x, rf1.z};
    const float rys[4] = {rf0.y, rf0.w, rf1.y, rf1.w};

    float accA = 0.f, accB = 0.f;
#pragma unroll
    for (int l = 0; l < NLEV; l++) {
        const int   Wi = dims[l], Hi = dims[l];
        const float Wf = (float)Wi, Hf = (float)Hi;
        const float* base = fm + (size_t)starts[l] * FMSTRIDE
                               + n * CDIM + h * DH + lane;
        const float rx = rxs[l], ry = rys[l];
#pragma unroll
        for (int p = 0; p < NPTS; p++) {
            const int pt = l * 4 + p;
            const float ox  = __shfl_sync(0xffffffffu, offv, 2 * pt);
            const float oy  = __shfl_sync(0xffffffffu, offv, 2 * pt + 1);
            const float apt = __shfl_sync(0xffffffffu, wgt,  pt);

            const float x = (rx + ox / Wf) * Wf - 0.5f;
            const float y = (ry + oy / Hf) * Hf - 0.5f;

            const float x0f = floorf(x), y0f = floorf(y);
            const int   x0 = (int)x0f,  y0 = (int)y0f;
            const float wx = x - x0f,   wy = y - y0f;

            const bool xv0 = (x0 >= 0) & (x0 < Wi);
            const bool xv1 = (x0 >= -1) & (x0 < Wi - 1);
            const bool yv0 = (y0 >= 0) & (y0 < Hi);
            const bool yv1 = (y0 >= -1) & (y0 < Hi - 1);

            const float* r0p = base + (size_t)(y0 * Wi) * FMSTRIDE;
            const float* r1p = r0p + (size_t)Wi * FMSTRIDE;

            // Flat independent predicated loads -> @P LDG, full MLP
            float v00 = 0.f, v01 = 0.f, v10 = 0.f, v11 = 0.f;
            if (xv0 & yv0) v00 = r0p[(size_t)x0 * FMSTRIDE];
            if (xv1 & yv0) v01 = r0p[(size_t)(x0 + 1) * FMSTRIDE];
            if (xv0 & yv1) v10 = r1p[(size_t)x0 * FMSTRIDE];
            if (xv1 & yv1) v11 = r1p[(size_t)(x0 + 1) * FMSTRIDE];

            const float w00 = (1.f - wx) * (1.f - wy) * apt;
            const float w01 = wx         * (1.f - wy) * apt;
            const float w10 = (1.f - wx) * wy         * apt;
            const float w11 = wx         * wy         * apt;

            accA = fmaf(v00, w00, accA);
            accB = fmaf(v01, w01, accB);
            accA = fmaf(v10, w10, accA);
            accB = fmaf(v11, w11, accB);
        }
    }
    g_agg[r * 256 + h * 32 + lane] = accA + accB;
}

// ---------------------------------------------------------------------------
// Launch
// ---------------------------------------------------------------------------
extern "C" void kernel_launch(void* const* d_in, const int* in_sizes, int n_in,
                              void* d_out, int out_size) {
    const float* query   = (const float*)d_in[0];
    const float* refpts  = (const float*)d_in[1];
    const float* fmaps   = (const float*)d_in[2];
    const float* W_off   = (const float*)d_in[4];
    const float* b_off   = (const float*)d_in[5];
    const float* W_attn  = (const float*)d_in[6];
    const float* b_attn  = (const float*)d_in[7];
    const float* W_out   = (const float*)d_in[8];
    const float* b_out   = (const float*)d_in[9];
    float* out = (float*)d_out;

    qproj_kernel<<<dim3(3, MROWS / 128), 256>>>(query, W_off, b_off, W_attn, b_attn);
    sample_kernel<<<MROWS, 256>>>(refpts, fmaps);
    outproj_kernel<<<dim3(2, MROWS / 128), 256>>>(W_out, b_out, out);
}

// round 6
// speedup vs baseline: 1.9000x; 1.3435x over previous
#include <cuda_runtime.h>
#include <cstdint>

// ---------------------------------------------------------------------------
// Problem constants
// ---------------------------------------------------------------------------
#define LQ      4096
#define NB      8
#define CDIM    256
#define MROWS   (LQ * NB)          // 32768
#define NHEADS  8
#define NLEV    4
#define NPTS    4
#define DH      32
#define FMSTRIDE (NB * CDIM)       // 2048 floats per spatial cell row

// ---------------------------------------------------------------------------
// Scratch (__device__ globals; cudaMalloc forbidden)
// ---------------------------------------------------------------------------
__device__ float g_off[MROWS * 256];
__device__ float g_logits[MROWS * 128];
__device__ float g_agg[MROWS * 256];

// ---------------------------------------------------------------------------
// TF32 helpers
// ---------------------------------------------------------------------------
__device__ __forceinline__ uint32_t f2tf32(float f) {
    uint32_t u;
    asm("cvt.rna.tf32.f32 %0, %1;" : "=r"(u) : "f"(f));
    return u;
}

__device__ __forceinline__ void mma_tf32(float* c, const uint32_t* a, const uint32_t* b) {
    asm volatile(
        "mma.sync.aligned.m16n8k8.row.col.f32.tf32.tf32.f32 "
        "{%0,%1,%2,%3}, {%4,%5,%6,%7}, {%8,%9}, {%0,%1,%2,%3};"
        : "+f"(c[0]), "+f"(c[1]), "+f"(c[2]), "+f"(c[3])
        : "r"(a[0]), "r"(a[1]), "r"(a[2]), "r"(a[3]), "r"(b[0]), "r"(b[1]));
}

// ---------------------------------------------------------------------------
// TF32 MMA GEMM core: 128x128 tile, BK=16, 256 threads (8 warps in 4x2 grid),
// warp tile 32(m) x 64(n) = 2 m-frags x 8 n-frags of m16n8k8.
// ---------------------------------------------------------------------------
__device__ __forceinline__ void mma_gemm_core(const float* __restrict__ Ab,
                                              const float* __restrict__ Bb,
                                              const float* __restrict__ biasp,
                                              float* __restrict__ Cb,
                                              int ldb, int ldc, int K) {
    __shared__ uint32_t As[2][128][20];
    __shared__ uint32_t Bs[2][16][136];

    const int tid  = threadIdx.x;
    const int wid  = tid >> 5;
    const int lane = tid & 31;
    const int gid  = lane >> 2;
    const int tig  = lane & 3;
    const int wm   = (wid & 3) * 32;
    const int wn   = (wid >> 2) * 64;

    const int arow = tid >> 1;
    const int acol = (tid & 1) * 8;
    const int brow = tid >> 5;
    const int bcol = (tid & 31) * 4;

    float acc[2][8][4];
#pragma unroll
    for (int i = 0; i < 2; i++)
#pragma unroll
        for (int j = 0; j < 8; j++)
#pragma unroll
            for (int v = 0; v < 4; v++) acc[i][j][v] = 0.f;

    const int nk = K / 16;

    float4 a0 = *(const float4*)(Ab + (size_t)arow * K + acol);
    float4 a1 = *(const float4*)(Ab + (size_t)arow * K + acol + 4);
    float4 b0 = *(const float4*)(Bb + (size_t)brow * ldb + bcol);
    float4 b1 = *(const float4*)(Bb + (size_t)(brow + 8) * ldb + bcol);

    {
        uint32_t* ap = &As[0][arow][acol];
        ap[0] = f2tf32(a0.x); ap[1] = f2tf32(a0.y); ap[2] = f2tf32(a0.z); ap[3] = f2tf32(a0.w);
        ap[4] = f2tf32(a1.x); ap[5] = f2tf32(a1.y); ap[6] = f2tf32(a1.z); ap[7] = f2tf32(a1.w);
        uint32_t* bp0 = &Bs[0][brow][bcol];
        bp0[0] = f2tf32(b0.x); bp0[1] = f2tf32(b0.y); bp0[2] = f2tf32(b0.z); bp0[3] = f2tf32(b0.w);
        uint32_t* bp1 = &Bs[0][brow + 8][bcol];
        bp1[0] = f2tf32(b1.x); bp1[1] = f2tf32(b1.y); bp1[2] = f2tf32(b1.z); bp1[3] = f2tf32(b1.w);
    }
    __syncthreads();

    for (int kb = 0; kb < nk; kb++) {
        const int cur = kb & 1;
        const bool more = (kb + 1) < nk;
        if (more) {
            const int k0 = (kb + 1) * 16;
            a0 = *(const float4*)(Ab + (size_t)arow * K + k0 + acol);
            a1 = *(const float4*)(Ab + (size_t)arow * K + k0 + acol + 4);
            b0 = *(const float4*)(Bb + (size_t)(k0 + brow) * ldb + bcol);
            b1 = *(const float4*)(Bb + (size_t)(k0 + brow + 8) * ldb + bcol);
        }

#pragma unroll
        for (int ks = 0; ks < 2; ks++) {
            const int kk = ks * 8;
            uint32_t af[2][4];
#pragma unroll
            for (int mi = 0; mi < 2; mi++) {
                const int r = wm + mi * 16 + gid;
                af[mi][0] = As[cur][r][kk + tig];
                af[mi][1] = As[cur][r + 8][kk + tig];
                af[mi][2] = As[cur][r][kk + tig + 4];
                af[mi][3] = As[cur][r + 8][kk + tig + 4];
            }
            uint32_t bf[8][2];
#pragma unroll
            for (int ni = 0; ni < 8; ni++) {
                const int c = wn + ni * 8 + gid;
                bf[ni][0] = Bs[cur][kk + tig][c];
                bf[ni][1] = Bs[cur][kk + tig + 4][c];
            }
#pragma unroll
            for (int mi = 0; mi < 2; mi++)
#pragma unroll
                for (int ni = 0; ni < 8; ni++)
                    mma_tf32(acc[mi][ni], af[mi], bf[ni]);
        }

        if (more) {
            const int nxt = 1 - cur;
            uint32_t* ap = &As[nxt][arow][acol];
            ap[0] = f2tf32(a0.x); ap[1] = f2tf32(a0.y); ap[2] = f2tf32(a0.z); ap[3] = f2tf32(a0.w);
            ap[4] = f2tf32(a1.x); ap[5] = f2tf32(a1.y); ap[6] = f2tf32(a1.z); ap[7] = f2tf32(a1.w);
            uint32_t* bp0 = &Bs[nxt][brow][bcol];
            bp0[0] = f2tf32(b0.x); bp0[1] = f2tf32(b0.y); bp0[2] = f2tf32(b0.z); bp0[3] = f2tf32(b0.w);
            uint32_t* bp1 = &Bs[nxt][brow + 8][bcol];
            bp1[0] = f2tf32(b1.x); bp1[1] = f2tf32(b1.y); bp1[2] = f2tf32(b1.z); bp1[3] = f2tf32(b1.w);
            __syncthreads();
        }
    }

#pragma unroll
    for (int mi = 0; mi < 2; mi++) {
        const int r = wm + mi * 16 + gid;
#pragma unroll
        for (int ni = 0; ni < 8; ni++) {
            const int c = wn + ni * 8 + tig * 2;
            const float bia0 = biasp[c], bia1 = biasp[c + 1];
            float2 lo = make_float2(acc[mi][ni][0] + bia0, acc[mi][ni][1] + bia1);
            float2 hi = make_float2(acc[mi][ni][2] + bia0, acc[mi][ni][3] + bia1);
            *(float2*)(Cb + (size_t)r * ldc + c)       = lo;
            *(float2*)(Cb + (size_t)(r + 8) * ldc + c) = hi;
        }
    }
}

// Fused Q-projection: bx in {0,1} -> W_off col tiles; bx==2 -> W_attn
__global__ __launch_bounds__(256)
void qproj_kernel(const float* __restrict__ Q,
                  const float* __restrict__ Woff, const float* __restrict__ boff,
                  const float* __restrict__ Wattn, const float* __restrict__ battn) {
    const int bx = blockIdx.x, by = blockIdx.y;
    const float* Ab = Q + (size_t)by * 128 * 256;
    if (bx < 2) {
        mma_gemm_core(Ab, Woff + bx * 128, boff + bx * 128,
                      g_off + (size_t)by * 128 * 256 + bx * 128, 256, 256, 256);
    } else {
        mma_gemm_core(Ab, Wattn, battn,
                      g_logits + (size_t)by * 128 * 128, 128, 128, 256);
    }
}

__global__ __launch_bounds__(256)
void outproj_kernel(const float* __restrict__ W, const float* __restrict__ bias,
                    float* __restrict__ out) {
    const int bx = blockIdx.x, by = blockIdx.y;
    mma_gemm_core(g_agg + (size_t)by * 128 * 256, W + bx * 128, bias + bx * 128,
                  out + (size_t)by * 128 * 256 + bx * 128, 256, 256, 256);
}

// ---------------------------------------------------------------------------
// Sampling (vectorized gather): one block per query row, one warp per head.
// Lane roles: g = lane>>3 selects the bilinear tap (00/01/10/11),
//             s = lane&7 selects the channel quad (channels 4s..4s+3).
// Per point the whole warp issues ONE LDG.E.128 covering all 4 taps x 32 ch.
// Cross-tap reduction via shfl_xor(8,16); lanes 0..7 store float4 results.
// ---------------------------------------------------------------------------
__global__ __launch_bounds__(256)
void sample_kernel(const float* __restrict__ refpts,
                   const float* __restrict__ fm) {
    const int r    = blockIdx.x;
    const int h    = threadIdx.x >> 5;
    const int lane = threadIdx.x & 31;
    const int g    = lane >> 3;       // tap group 0..3
    const int s    = lane & 7;        // channel quad 0..7
    const int gx   = g & 1;           // +0/+1 in x
    const int gy   = g >> 1;          // +0/+1 in y
    const int n    = r & (NB - 1);
    const int lq   = r >> 3;

    const float offv  = g_off[r * 256 + h * 32 + lane];
    const float logit = g_logits[r * 128 + h * 16 + (lane & 15)];

    // Softmax over 16 logits (replicated across warp halves)
    float mx = logit;
#pragma unroll
    for (int sh = 8; sh > 0; sh >>= 1)
        mx = fmaxf(mx, __shfl_xor_sync(0xffffffffu, mx, sh));
    float ex = __expf(logit - mx);
    float sm = ex;
#pragma unroll
    for (int sh = 8; sh > 0; sh >>= 1)
        sm += __shfl_xor_sync(0xffffffffu, sm, sh);
    const float wgt = ex / sm;

    const int starts[4] = {0, 10000, 12500, 13125};
    const int dims[4]   = {100, 50, 25, 13};

    const float4* refv = (const float4*)(refpts + ((size_t)(n * LQ + lq) * NLEV) * 2);
    const float4 rf0 = refv[0], rf1 = refv[1];
    const float rxs[4] = {rf0.x, rf0.z, rf1.x, rf1.z};
    const float rys[4] = {rf0.y, rf0.w, rf1.y, rf1.w};

    float4 acc = make_float4(0.f, 0.f, 0.f, 0.f);

#pragma unroll
    for (int l = 0; l < NLEV; l++) {
        const int   Wi = dims[l], Hi = dims[l];
        const float Wf = (float)Wi, Hf = (float)Hi;
        // base for this lane's channel quad within this level
        const float* base = fm + (size_t)starts[l] * FMSTRIDE
                               + n * CDIM + h * DH + s * 4;
        const float rx = rxs[l], ry = rys[l];
#pragma unroll
        for (int p = 0; p < NPTS; p++) {
            const int pt = l * 4 + p;
            const float ox  = __shfl_sync(0xffffffffu, offv, 2 * pt);
            const float oy  = __shfl_sync(0xffffffffu, offv, 2 * pt + 1);
            const float apt = __shfl_sync(0xffffffffu, wgt,  pt);

            const float x = (rx + ox / Wf) * Wf - 0.5f;
            const float y = (ry + oy / Hf) * Hf - 0.5f;

            const float x0f = floorf(x), y0f = floorf(y);
            const int   x0 = (int)x0f,  y0 = (int)y0f;
            const float wx = x - x0f,   wy = y - y0f;

            // This lane's tap
            const int xi = x0 + gx;
            const int yi = y0 + gy;
            const bool valid = (xi >= 0) & (xi < Wi) & (yi >= 0) & (yi < Hi);

            float4 v = make_float4(0.f, 0.f, 0.f, 0.f);
            if (valid) {
                const long long cell = (long long)yi * Wi + xi;
                v = *(const float4*)(base + cell * FMSTRIDE);
            }

            const float w = (gx ? wx : 1.f - wx) * (gy ? wy : 1.f - wy) * apt;
            acc.x = fmaf(v.x, w, acc.x);
            acc.y = fmaf(v.y, w, acc.y);
            acc.z = fmaf(v.z, w, acc.z);
            acc.w = fmaf(v.w, w, acc.w);
        }
    }

    // Fold the 4 tap groups: lanes differing in bits 3,4 hold same channels
#pragma unroll
    for (int m = 8; m <= 16; m <<= 1) {
        acc.x += __shfl_xor_sync(0xffffffffu, acc.x, m);
        acc.y += __shfl_xor_sync(0xffffffffu, acc.y, m);
        acc.z += __shfl_xor_sync(0xffffffffu, acc.z, m);
        acc.w += __shfl_xor_sync(0xffffffffu, acc.w, m);
    }
    if (lane < 8)
        *(float4*)(g_agg + (size_t)r * 256 + h * 32 + s * 4) = acc;
}

// ---------------------------------------------------------------------------
// Launch
// ---------------------------------------------------------------------------
extern "C" void kernel_launch(void* const* d_in, const int* in_sizes, int n_in,
                              void* d_out, int out_size) {
    const float* query   = (const float*)d_in[0];
    const float* refpts  = (const float*)d_in[1];
    const float* fmaps   = (const float*)d_in[2];
    const float* W_off   = (const float*)d_in[4];
    const float* b_off   = (const float*)d_in[5];
    const float* W_attn  = (const float*)d_in[6];
    const float* b_attn  = (const float*)d_in[7];
    const float* W_out   = (const float*)d_in[8];
    const float* b_out   = (const float*)d_in[9];
    float* out = (float*)d_out;

    qproj_kernel<<<dim3(3, MROWS / 128), 256>>>(query, W_off, b_off, W_attn, b_attn);
    sample_kernel<<<MROWS, 256>>>(refpts, fmaps);
    outproj_kernel<<<dim3(2, MROWS / 128), 256>>>(W_out, b_out, out);
}

// round 7
// speedup vs baseline: 2.1002x; 1.1054x over previous
#include <cuda_runtime.h>
#include <cuda_fp16.h>
#include <cstdint>

// ---------------------------------------------------------------------------
// Problem constants
// ---------------------------------------------------------------------------
#define LQ      4096
#define NB      8
#define CDIM    256
#define MROWS   (LQ * NB)          // 32768
#define NHEADS  8
#define NLEV    4
#define NPTS    4
#define DH      32
#define FMSTRIDE (NB * CDIM)       // 2048 elems per spatial cell row
#define LTOTAL  13294
#define FMELEMS (LTOTAL * FMSTRIDE)   // 27,226,112

// ---------------------------------------------------------------------------
// Scratch (__device__ globals; cudaMalloc forbidden)
// ---------------------------------------------------------------------------
__device__ float  g_off[MROWS * 256];
__device__ float  g_logits[MROWS * 128];
__device__ float  g_agg[MROWS * 256];
__device__ __half g_fm16[FMELEMS];     // fp16 copy of feature maps (~54 MB)

// ---------------------------------------------------------------------------
// TF32 helpers
// ---------------------------------------------------------------------------
__device__ __forceinline__ uint32_t f2tf32(float f) {
    uint32_t u;
    asm("cvt.rna.tf32.f32 %0, %1;" : "=r"(u) : "f"(f));
    return u;
}

__device__ __forceinline__ void mma_tf32(float* c, const uint32_t* a, const uint32_t* b) {
    asm volatile(
        "mma.sync.aligned.m16n8k8.row.col.f32.tf32.tf32.f32 "
        "{%0,%1,%2,%3}, {%4,%5,%6,%7}, {%8,%9}, {%0,%1,%2,%3};"
        : "+f"(c[0]), "+f"(c[1]), "+f"(c[2]), "+f"(c[3])
        : "r"(a[0]), "r"(a[1]), "r"(a[2]), "r"(a[3]), "r"(b[0]), "r"(b[1]));
}

// ---------------------------------------------------------------------------
// fm fp32 -> fp16 convert kernel (graph-capturable, deterministic)
// ---------------------------------------------------------------------------
__global__ __launch_bounds__(256)
void fmconv_kernel(const float* __restrict__ fm) {
    const size_t i = ((size_t)blockIdx.x * 256 + threadIdx.x) * 4;
    if (i < FMELEMS) {
        const float4 v = *(const float4*)(fm + i);
        __half2 lo = __floats2half2_rn(v.x, v.y);
        __half2 hi = __floats2half2_rn(v.z, v.w);
        uint2 pk;
        pk.x = *(const uint32_t*)&lo;
        pk.y = *(const uint32_t*)&hi;
        *(uint2*)(g_fm16 + i) = pk;
    }
}

// ---------------------------------------------------------------------------
// TF32 MMA GEMM core: 128x128 tile, BK=16, 256 threads (8 warps in 4x2 grid),
// warp tile 32(m) x 64(n) = 2 m-frags x 8 n-frags of m16n8k8.
// ---------------------------------------------------------------------------
__device__ __forceinline__ void mma_gemm_core(const float* __restrict__ Ab,
                                              const float* __restrict__ Bb,
                                              const float* __restrict__ biasp,
                                              float* __restrict__ Cb,
                                              int ldb, int ldc, int K) {
    __shared__ uint32_t As[2][128][20];
    __shared__ uint32_t Bs[2][16][136];

    const int tid  = threadIdx.x;
    const int wid  = tid >> 5;
    const int lane = tid & 31;
    const int gid  = lane >> 2;
    const int tig  = lane & 3;
    const int wm   = (wid & 3) * 32;
    const int wn   = (wid >> 2) * 64;

    const int arow = tid >> 1;
    const int acol = (tid & 1) * 8;
    const int brow = tid >> 5;
    const int bcol = (tid & 31) * 4;

    float acc[2][8][4];
#pragma unroll
    for (int i = 0; i < 2; i++)
#pragma unroll
        for (int j = 0; j < 8; j++)
#pragma unroll
            for (int v = 0; v < 4; v++) acc[i][j][v] = 0.f;

    const int nk = K / 16;

    float4 a0 = *(const float4*)(Ab + (size_t)arow * K + acol);
    float4 a1 = *(const float4*)(Ab + (size_t)arow * K + acol + 4);
    float4 b0 = *(const float4*)(Bb + (size_t)brow * ldb + bcol);
    float4 b1 = *(const float4*)(Bb + (size_t)(brow + 8) * ldb + bcol);

    {
        uint32_t* ap = &As[0][arow][acol];
        ap[0] = f2tf32(a0.x); ap[1] = f2tf32(a0.y); ap[2] = f2tf32(a0.z); ap[3] = f2tf32(a0.w);
        ap[4] = f2tf32(a1.x); ap[5] = f2tf32(a1.y); ap[6] = f2tf32(a1.z); ap[7] = f2tf32(a1.w);
        uint32_t* bp0 = &Bs[0][brow][bcol];
        bp0[0] = f2tf32(b0.x); bp0[1] = f2tf32(b0.y); bp0[2] = f2tf32(b0.z); bp0[3] = f2tf32(b0.w);
        uint32_t* bp1 = &Bs[0][brow + 8][bcol];
        bp1[0] = f2tf32(b1.x); bp1[1] = f2tf32(b1.y); bp1[2] = f2tf32(b1.z); bp1[3] = f2tf32(b1.w);
    }
    __syncthreads();

    for (int kb = 0; kb < nk; kb++) {
        const int cur = kb & 1;
        const bool more = (kb + 1) < nk;
        if (more) {
            const int k0 = (kb + 1) * 16;
            a0 = *(const float4*)(Ab + (size_t)arow * K + k0 + acol);
            a1 = *(const float4*)(Ab + (size_t)arow * K + k0 + acol + 4);
            b0 = *(const float4*)(Bb + (size_t)(k0 + brow) * ldb + bcol);
            b1 = *(const float4*)(Bb + (size_t)(k0 + brow + 8) * ldb + bcol);
        }

#pragma unroll
        for (int ks = 0; ks < 2; ks++) {
            const int kk = ks * 8;
            uint32_t af[2][4];
#pragma unroll
            for (int mi = 0; mi < 2; mi++) {
                const int r = wm + mi * 16 + gid;
                af[mi][0] = As[cur][r][kk + tig];
                af[mi][1] = As[cur][r + 8][kk + tig];
                af[mi][2] = As[cur][r][kk + tig + 4];
                af[mi][3] = As[cur][r + 8][kk + tig + 4];
            }
            uint32_t bf[8][2];
#pragma unroll
            for (int ni = 0; ni < 8; ni++) {
                const int c = wn + ni * 8 + gid;
                bf[ni][0] = Bs[cur][kk + tig][c];
                bf[ni][1] = Bs[cur][kk + tig + 4][c];
            }
#pragma unroll
            for (int mi = 0; mi < 2; mi++)
#pragma unroll
                for (int ni = 0; ni < 8; ni++)
                    mma_tf32(acc[mi][ni], af[mi], bf[ni]);
        }

        if (more) {
            const int nxt = 1 - cur;
            uint32_t* ap = &As[nxt][arow][acol];
            ap[0] = f2tf32(a0.x); ap[1] = f2tf32(a0.y); ap[2] = f2tf32(a0.z); ap[3] = f2tf32(a0.w);
            ap[4] = f2tf32(a1.x); ap[5] = f2tf32(a1.y); ap[6] = f2tf32(a1.z); ap[7] = f2tf32(a1.w);
            uint32_t* bp0 = &Bs[nxt][brow][bcol];
            bp0[0] = f2tf32(b0.x); bp0[1] = f2tf32(b0.y); bp0[2] = f2tf32(b0.z); bp0[3] = f2tf32(b0.w);
            uint32_t* bp1 = &Bs[nxt][brow + 8][bcol];
            bp1[0] = f2tf32(b1.x); bp1[1] = f2tf32(b1.y); bp1[2] = f2tf32(b1.z); bp1[3] = f2tf32(b1.w);
            __syncthreads();
        }
    }

#pragma unroll
    for (int mi = 0; mi < 2; mi++) {
        const int r = wm + mi * 16 + gid;
#pragma unroll
        for (int ni = 0; ni < 8; ni++) {
            const int c = wn + ni * 8 + tig * 2;
            const float bia0 = biasp[c], bia1 = biasp[c + 1];
            float2 lo = make_float2(acc[mi][ni][0] + bia0, acc[mi][ni][1] + bia1);
            float2 hi = make_float2(acc[mi][ni][2] + bia0, acc[mi][ni][3] + bia1);
            *(float2*)(Cb + (size_t)r * ldc + c)       = lo;
            *(float2*)(Cb + (size_t)(r + 8) * ldc + c) = hi;
        }
    }
}

// Fused Q-projection: bx in {0,1} -> W_off col tiles; bx==2 -> W_attn
__global__ __launch_bounds__(256)
void qproj_kernel(const float* __restrict__ Q,
                  const float* __restrict__ Woff, const float* __restrict__ boff,
                  const float* __restrict__ Wattn, const float* __restrict__ battn) {
    const int bx = blockIdx.x, by = blockIdx.y;
    const float* Ab = Q + (size_t)by * 128 * 256;
    if (bx < 2) {
        mma_gemm_core(Ab, Woff + bx * 128, boff + bx * 128,
                      g_off + (size_t)by * 128 * 256 + bx * 128, 256, 256, 256);
    } else {
        mma_gemm_core(Ab, Wattn, battn,
                      g_logits + (size_t)by * 128 * 128, 128, 128, 256);
    }
}

__global__ __launch_bounds__(256)
void outproj_kernel(const float* __restrict__ W, const float* __restrict__ bias,
                    float* __restrict__ out) {
    const int bx = blockIdx.x, by = blockIdx.y;
    mma_gemm_core(g_agg + (size_t)by * 128 * 256, W + bx * 128, bias + bx * 128,
                  out + (size_t)by * 128 * 256 + bx * 128, 256, 256, 256);
}

// ---------------------------------------------------------------------------
// Sampling (fp16 gather, 2 points per warp-iteration):
// lane layout: q = lane>>4 (point parity), g = (lane>>2)&3 (tap), s = lane&3
// (channel octet). Each lane loads ONE uint4 = 8 halves (16B) per iteration;
// warp covers 2 points x 4 taps x 32 channels. 8 iterations total.
// Reduction over tap+parity via shfl_xor(4,8,16); lanes 0..3 store 32B each.
// ---------------------------------------------------------------------------
__global__ __launch_bounds__(256)
void sample_kernel(const float* __restrict__ refpts) {
    const int r    = blockIdx.x;
    const int h    = threadIdx.x >> 5;
    const int lane = threadIdx.x & 31;
    const int q    = lane >> 4;        // point parity 0/1
    const int g    = (lane >> 2) & 3;  // tap group
    const int s    = lane & 3;         // channel octet 0..3
    const int gx   = g & 1;
    const int gy   = g >> 1;
    const int n    = r & (NB - 1);
    const int lq   = r >> 3;

    const float offv  = g_off[r * 256 + h * 32 + lane];
    const float logit = g_logits[r * 128 + h * 16 + (lane & 15)];

    // Softmax over 16 logits (replicated across warp halves)
    float mx = logit;
#pragma unroll
    for (int sh = 8; sh > 0; sh >>= 1)
        mx = fmaxf(mx, __shfl_xor_sync(0xffffffffu, mx, sh));
    float ex = __expf(logit - mx);
    float sm = ex;
#pragma unroll
    for (int sh = 8; sh > 0; sh >>= 1)
        sm += __shfl_xor_sync(0xffffffffu, sm, sh);
    const float wgt = ex / sm;

    const int starts[4] = {0, 10000, 12500, 13125};
    const int dims[4]   = {100, 50, 25, 13};

    const float4* refv = (const float4*)(refpts + ((size_t)(n * LQ + lq) * NLEV) * 2);
    const float4 rf0 = refv[0], rf1 = refv[1];
    const float rxs[4] = {rf0.x, rf0.z, rf1.x, rf1.z};
    const float rys[4] = {rf0.y, rf0.w, rf1.y, rf1.w};

    float acc[8];
#pragma unroll
    for (int k = 0; k < 8; k++) acc[k] = 0.f;

#pragma unroll
    for (int t = 0; t < 8; t++) {
        const int l  = t >> 1;               // level
        const int pt = l * 4 + (t & 1) * 2 + q;  // this lane's point
        const int Wi = dims[l], Hi = dims[l];
        const float Wf = (float)Wi, Hf = (float)Hi;
        const float rx = rxs[l], ry = rys[l];

        const float ox  = __shfl_sync(0xffffffffu, offv, 2 * pt);
        const float oy  = __shfl_sync(0xffffffffu, offv, 2 * pt + 1);
        const float apt = __shfl_sync(0xffffffffu, wgt,  pt);

        const float x = (rx + ox / Wf) * Wf - 0.5f;
        const float y = (ry + oy / Hf) * Hf - 0.5f;

        const float x0f = floorf(x), y0f = floorf(y);
        const int   x0 = (int)x0f,  y0 = (int)y0f;
        const float wx = x - x0f,   wy = y - y0f;

        const int xi = x0 + gx;
        const int yi = y0 + gy;
        const bool valid = (xi >= 0) & (xi < Wi) & (yi >= 0) & (yi < Hi);

        uint4 raw = make_uint4(0u, 0u, 0u, 0u);
        if (valid) {
            const long long cell = (long long)starts[l] + (long long)yi * Wi + xi;
            raw = *(const uint4*)(g_fm16 + cell * FMSTRIDE + n * CDIM + h * DH + s * 8);
        }

        const float w = (gx ? wx : 1.f - wx) * (gy ? wy : 1.f - wy) * apt;
        const float2 v0 = __half22float2(*(const __half2*)&raw.x);
        const float2 v1 = __half22float2(*(const __half2*)&raw.y);
        const float2 v2 = __half22float2(*(const __half2*)&raw.z);
        const float2 v3 = __half22float2(*(const __half2*)&raw.w);
        acc[0] = fmaf(v0.x, w, acc[0]); acc[1] = fmaf(v0.y, w, acc[1]);
        acc[2] = fmaf(v1.x, w, acc[2]); acc[3] = fmaf(v1.y, w, acc[3]);
        acc[4] = fmaf(v2.x, w, acc[4]); acc[5] = fmaf(v2.y, w, acc[5]);
        acc[6] = fmaf(v3.x, w, acc[6]); acc[7] = fmaf(v3.y, w, acc[7]);
    }

    // Fold taps (bits 2,3) and point parity (bit 4)
#pragma unroll
    for (int m = 4; m <= 16; m <<= 1) {
#pragma unroll
        for (int k = 0; k < 8; k++)
            acc[k] += __shfl_xor_sync(0xffffffffu, acc[k], m);
    }

    if (lane < 4) {
        float* dst = g_agg + (size_t)r * 256 + h * 32 + s * 8;
        *(float4*)(dst)     = make_float4(acc[0], acc[1], acc[2], acc[3]);
        *(float4*)(dst + 4) = make_float4(acc[4], acc[5], acc[6], acc[7]);
    }
}

// ---------------------------------------------------------------------------
// Launch
// ---------------------------------------------------------------------------
extern "C" void kernel_launch(void* const* d_in, const int* in_sizes, int n_in,
                              void* d_out, int out_size) {
    const float* query   = (const float*)d_in[0];
    const float* refpts  = (const float*)d_in[1];
    const float* fmaps   = (const float*)d_in[2];
    const float* W_off   = (const float*)d_in[4];
    const float* b_off   = (const float*)d_in[5];
    const float* W_attn  = (const float*)d_in[6];
    const float* b_attn  = (const float*)d_in[7];
    const float* W_out   = (const float*)d_in[8];
    const float* b_out   = (const float*)d_in[9];
    float* out = (float*)d_out;

    fmconv_kernel<<<(FMELEMS / 4 + 255) / 256, 256>>>(fmaps);
    qproj_kernel<<<dim3(3, MROWS / 128), 256>>>(query, W_off, b_off, W_attn, b_attn);
    sample_kernel<<<MROWS, 256>>>(refpts);
    outproj_kernel<<<dim3(2, MROWS / 128), 256>>>(W_out, b_out, out);
}

// round 8
// speedup vs baseline: 2.8254x; 1.3453x over previous
#include <cuda_runtime.h>
#include <cuda_fp16.h>
#include <cstdint>

// ---------------------------------------------------------------------------
// Problem constants
// ---------------------------------------------------------------------------
#define LQ      4096
#define NB      8
#define CDIM    256
#define MROWS   (LQ * NB)          // 32768
#define NHEADS  8
#define NLEV    4
#define NPTS    4
#define DH      32
#define FMSTRIDE (NB * CDIM)       // 2048 elems per spatial cell row
#define LTOTAL  13294
#define FMELEMS (LTOTAL * FMSTRIDE)   // 27,226,112

// ---------------------------------------------------------------------------
// Scratch (__device__ globals; cudaMalloc forbidden)
// ---------------------------------------------------------------------------
__device__ float  g_off[MROWS * 256];
__device__ float  g_logits[MROWS * 128];
__device__ float  g_agg[MROWS * 256];
__device__ __half g_fm16[FMELEMS];     // fp16 copy of feature maps (~54 MB)

// ---------------------------------------------------------------------------
// TF32 helpers
// ---------------------------------------------------------------------------
__device__ __forceinline__ uint32_t f2tf32(float f) {
    uint32_t u;
    asm("cvt.rna.tf32.f32 %0, %1;" : "=r"(u) : "f"(f));
    return u;
}

__device__ __forceinline__ void mma_tf32(float* c, const uint32_t* a, const uint32_t* b) {
    asm volatile(
        "mma.sync.aligned.m16n8k8.row.col.f32.tf32.tf32.f32 "
        "{%0,%1,%2,%3}, {%4,%5,%6,%7}, {%8,%9}, {%0,%1,%2,%3};"
        : "+f"(c[0]), "+f"(c[1]), "+f"(c[2]), "+f"(c[3])
        : "r"(a[0]), "r"(a[1]), "r"(a[2]), "r"(a[3]), "r"(b[0]), "r"(b[1]));
}

// ---------------------------------------------------------------------------
// TF32 MMA GEMM core: 128x128 tile, BK=16, 256 threads (8 warps, 4x2 grid)
// ---------------------------------------------------------------------------
__device__ __forceinline__ void mma_gemm_core(const float* __restrict__ Ab,
                                              const float* __restrict__ Bb,
                                              const float* __restrict__ biasp,
                                              float* __restrict__ Cb,
                                              int ldb, int ldc, int K) {
    __shared__ uint32_t As[2][128][20];
    __shared__ uint32_t Bs[2][16][136];

    const int tid  = threadIdx.x;
    const int wid  = tid >> 5;
    const int lane = tid & 31;
    const int gid  = lane >> 2;
    const int tig  = lane & 3;
    const int wm   = (wid & 3) * 32;
    const int wn   = (wid >> 2) * 64;

    const int arow = tid >> 1;
    const int acol = (tid & 1) * 8;
    const int brow = tid >> 5;
    const int bcol = (tid & 31) * 4;

    float acc[2][8][4];
#pragma unroll
    for (int i = 0; i < 2; i++)
#pragma unroll
        for (int j = 0; j < 8; j++)
#pragma unroll
            for (int v = 0; v < 4; v++) acc[i][j][v] = 0.f;

    const int nk = K / 16;

    float4 a0 = *(const float4*)(Ab + (size_t)arow * K + acol);
    float4 a1 = *(const float4*)(Ab + (size_t)arow * K + acol + 4);
    float4 b0 = *(const float4*)(Bb + (size_t)brow * ldb + bcol);
    float4 b1 = *(const float4*)(Bb + (size_t)(brow + 8) * ldb + bcol);

    {
        uint32_t* ap = &As[0][arow][acol];
        ap[0] = f2tf32(a0.x); ap[1] = f2tf32(a0.y); ap[2] = f2tf32(a0.z); ap[3] = f2tf32(a0.w);
        ap[4] = f2tf32(a1.x); ap[5] = f2tf32(a1.y); ap[6] = f2tf32(a1.z); ap[7] = f2tf32(a1.w);
        uint32_t* bp0 = &Bs[0][brow][bcol];
        bp0[0] = f2tf32(b0.x); bp0[1] = f2tf32(b0.y); bp0[2] = f2tf32(b0.z); bp0[3] = f2tf32(b0.w);
        uint32_t* bp1 = &Bs[0][brow + 8][bcol];
        bp1[0] = f2tf32(b1.x); bp1[1] = f2tf32(b1.y); bp1[2] = f2tf32(b1.z); bp1[3] = f2tf32(b1.w);
    }
    __syncthreads();

    for (int kb = 0; kb < nk; kb++) {
        const int cur = kb & 1;
        const bool more = (kb + 1) < nk;
        if (more) {
            const int k0 = (kb + 1) * 16;
            a0 = *(const float4*)(Ab + (size_t)arow * K + k0 + acol);
            a1 = *(const float4*)(Ab + (size_t)arow * K + k0 + acol + 4);
            b0 = *(const float4*)(Bb + (size_t)(k0 + brow) * ldb + bcol);
            b1 = *(const float4*)(Bb + (size_t)(k0 + brow + 8) * ldb + bcol);
        }

#pragma unroll
        for (int ks = 0; ks < 2; ks++) {
            const int kk = ks * 8;
            uint32_t af[2][4];
#pragma unroll
            for (int mi = 0; mi < 2; mi++) {
                const int r = wm + mi * 16 + gid;
                af[mi][0] = As[cur][r][kk + tig];
                af[mi][1] = As[cur][r + 8][kk + tig];
                af[mi][2] = As[cur][r][kk + tig + 4];
                af[mi][3] = As[cur][r + 8][kk + tig + 4];
            }
            uint32_t bf[8][2];
#pragma unroll
            for (int ni = 0; ni < 8; ni++) {
                const int c = wn + ni * 8 + gid;
                bf[ni][0] = Bs[cur][kk + tig][c];
                bf[ni][1] = Bs[cur][kk + tig + 4][c];
            }
#pragma unroll
            for (int mi = 0; mi < 2; mi++)
#pragma unroll
                for (int ni = 0; ni < 8; ni++)
                    mma_tf32(acc[mi][ni], af[mi], bf[ni]);
        }

        if (more) {
            const int nxt = 1 - cur;
            uint32_t* ap = &As[nxt][arow][acol];
            ap[0] = f2tf32(a0.x); ap[1] = f2tf32(a0.y); ap[2] = f2tf32(a0.z); ap[3] = f2tf32(a0.w);
            ap[4] = f2tf32(a1.x); ap[5] = f2tf32(a1.y); ap[6] = f2tf32(a1.z); ap[7] = f2tf32(a1.w);
            uint32_t* bp0 = &Bs[nxt][brow][bcol];
            bp0[0] = f2tf32(b0.x); bp0[1] = f2tf32(b0.y); bp0[2] = f2tf32(b0.z); bp0[3] = f2tf32(b0.w);
            uint32_t* bp1 = &Bs[nxt][brow + 8][bcol];
            bp1[0] = f2tf32(b1.x); bp1[1] = f2tf32(b1.y); bp1[2] = f2tf32(b1.z); bp1[3] = f2tf32(b1.w);
            __syncthreads();
        }
    }

#pragma unroll
    for (int mi = 0; mi < 2; mi++) {
        const int r = wm + mi * 16 + gid;
#pragma unroll
        for (int ni = 0; ni < 8; ni++) {
            const int c = wn + ni * 8 + tig * 2;
            const float bia0 = biasp[c], bia1 = biasp[c + 1];
            float2 lo = make_float2(acc[mi][ni][0] + bia0, acc[mi][ni][1] + bia1);
            float2 hi = make_float2(acc[mi][ni][2] + bia0, acc[mi][ni][3] + bia1);
            *(float2*)(Cb + (size_t)r * ldc + c)       = lo;
            *(float2*)(Cb + (size_t)(r + 8) * ldc + c) = hi;
        }
    }
}

// ---------------------------------------------------------------------------
// Fused Q-projection + fm->fp16 conversion.
// bx in {0,1}: W_off col tiles. bx==2: W_attn. bx in {3,4}: conversion blocks
// (512 total, grid-stride over FMELEMS/4 float4s). Conversion (DRAM-bound)
// overlaps with the tensor-bound GEMM inside one launch.
// ---------------------------------------------------------------------------
__global__ __launch_bounds__(256)
void qproj_kernel(const float* __restrict__ Q,
                  const float* __restrict__ Woff, const float* __restrict__ boff,
                  const float* __restrict__ Wattn, const float* __restrict__ battn,
                  const float* __restrict__ fm) {
    const int bx = blockIdx.x, by = blockIdx.y;
    if (bx < 2) {
        mma_gemm_core(Q + (size_t)by * 128 * 256, Woff + bx * 128, boff + bx * 128,
                      g_off + (size_t)by * 128 * 256 + bx * 128, 256, 256, 256);
    } else if (bx == 2) {
        mma_gemm_core(Q + (size_t)by * 128 * 256, Wattn, battn,
                      g_logits + (size_t)by * 128 * 128, 128, 128, 256);
    } else {
        const int cb = (bx - 3) * 256 + by;           // 0..511 conv block id
        const size_t nvec = FMELEMS / 4;              // float4 count
        for (size_t i = (size_t)cb * 256 + threadIdx.x; i < nvec; i += 512 * 256) {
            const float4 v = *(const float4*)(fm + i * 4);
            __half2 lo = __floats2half2_rn(v.x, v.y);
            __half2 hi = __floats2half2_rn(v.z, v.w);
            uint2 pk;
            pk.x = *(const uint32_t*)&lo;
            pk.y = *(const uint32_t*)&hi;
            *(uint2*)(g_fm16 + i * 4) = pk;
        }
    }
}

__global__ __launch_bounds__(256)
void outproj_kernel(const float* __restrict__ W, const float* __restrict__ bias,
                    float* __restrict__ out) {
    const int bx = blockIdx.x, by = blockIdx.y;
    mma_gemm_core(g_agg + (size_t)by * 128 * 256, W + bx * 128, bias + bx * 128,
                  out + (size_t)by * 128 * 256 + bx * 128, 256, 256, 256);
}

// ---------------------------------------------------------------------------
// Sampling, two-phase.
// Phase 1 (threads 0..127): thread j = h*16+pt computes softmax weight,
// sampling coords, and per-tap {absolute cell offset (clamped-safe), weight
// with validity folded} -> 4KB smem.
// Phase 2 (8 warps = 8 heads): lane = (q=pt parity, g=tap, s=channel octet).
// Inner loop: 2 LDS + 1 LDG.128 (fp16 x8) + 8 FMA. No shfl, no branches.
// ---------------------------------------------------------------------------
__global__ __launch_bounds__(256)
void sample_kernel(const float* __restrict__ refpts) {
    __shared__ int   s_cell[NHEADS][16][4];
    __shared__ float s_w[NHEADS][16][4];

    const int r  = blockIdx.x;
    const int n  = r & (NB - 1);
    const int lq = r >> 3;

    const int tid = threadIdx.x;

    // ---- Phase 1 ----
    if (tid < 128) {
        const int h  = tid >> 4;
        const int pt = tid & 15;
        const int l  = pt >> 2;

        const int starts[4] = {0, 10000, 12500, 13125};
        const int dims[4]   = {100, 50, 25, 13};
        const int Wi = dims[l], Hi = dims[l];
        const float Wf = (float)Wi, Hf = (float)Hi;

        // softmax over the 16 logits of this head (16-wide butterfly)
        const float logit = g_logits[r * 128 + tid];
        float mx = logit;
#pragma unroll
        for (int sh = 8; sh > 0; sh >>= 1)
            mx = fmaxf(mx, __shfl_xor_sync(0xffffffffu, mx, sh));
        float ex = __expf(logit - mx);
        float sm = ex;
#pragma unroll
        for (int sh = 8; sh > 0; sh >>= 1)
            sm += __shfl_xor_sync(0xffffffffu, sm, sh);
        const float wgt = ex / sm;

        const float2 off = ((const float2*)g_off)[(size_t)r * 128 + tid];
        const float2 ref = ((const float2*)refpts)[(size_t)(n * LQ + lq) * NLEV + l];

        const float x = (ref.x + off.x / Wf) * Wf - 0.5f;
        const float y = (ref.y + off.y / Hf) * Hf - 0.5f;
        const float x0f = floorf(x), y0f = floorf(y);
        const int   x0 = (int)x0f,  y0 = (int)y0f;
        const float wx = x - x0f,   wy = y - y0f;

#pragma unroll
        for (int g = 0; g < 4; g++) {
            const int xi = x0 + (g & 1);
            const int yi = y0 + (g >> 1);
            const bool valid = (xi >= 0) & (xi < Wi) & (yi >= 0) & (yi < Hi);
            const int xc = min(max(xi, 0), Wi - 1);
            const int yc = min(max(yi, 0), Hi - 1);
            s_cell[h][pt][g] = (starts[l] + yc * Wi + xc) * FMSTRIDE;
            const float w = ((g & 1) ? wx : 1.f - wx)
                          * ((g >> 1) ? wy : 1.f - wy) * wgt;
            s_w[h][pt][g] = valid ? w : 0.f;
        }
    }
    __syncthreads();

    // ---- Phase 2 ----
    const int h    = tid >> 5;
    const int lane = tid & 31;
    const int q    = lane >> 4;        // point parity
    const int g    = (lane >> 2) & 3;  // tap
    const int s    = lane & 3;         // channel octet

    const __half* gbase = g_fm16 + n * CDIM + h * DH + s * 8;

    float acc[8];
#pragma unroll
    for (int k = 0; k < 8; k++) acc[k] = 0.f;

#pragma unroll
    for (int t = 0; t < 8; t++) {
        const int pt = t * 2 + q;
        const int   cell = s_cell[h][pt][g];
        const float w    = s_w[h][pt][g];

        const uint4 raw = *(const uint4*)(gbase + cell);
        const float2 v0 = __half22float2(*(const __half2*)&raw.x);
        const float2 v1 = __half22float2(*(const __half2*)&raw.y);
        const float2 v2 = __half22float2(*(const __half2*)&raw.z);
        const float2 v3 = __half22float2(*(const __half2*)&raw.w);
        acc[0] = fmaf(v0.x, w, acc[0]); acc[1] = fmaf(v0.y, w, acc[1]);
        acc[2] = fmaf(v1.x, w, acc[2]); acc[3] = fmaf(v1.y, w, acc[3]);
        acc[4] = fmaf(v2.x, w, acc[4]); acc[5] = fmaf(v2.y, w, acc[5]);
        acc[6] = fmaf(v3.x, w, acc[6]); acc[7] = fmaf(v3.y, w, acc[7]);
    }

    // Fold taps (bits 2,3) and point parity (bit 4)
#pragma unroll
    for (int m = 4; m <= 16; m <<= 1) {
#pragma unroll
        for (int k = 0; k < 8; k++)
            acc[k] += __shfl_xor_sync(0xffffffffu, acc[k], m);
    }

    if (lane < 4) {
        float* dst = g_agg + (size_t)r * 256 + h * 32 + s * 8;
        *(float4*)(dst)     = make_float4(acc[0], acc[1], acc[2], acc[3]);
        *(float4*)(dst + 4) = make_float4(acc[4], acc[5], acc[6], acc[7]);
    }
}

// ---------------------------------------------------------------------------
// Launch
// ---------------------------------------------------------------------------
extern "C" void kernel_launch(void* const* d_in, const int* in_sizes, int n_in,
                              void* d_out, int out_size) {
    const float* query   = (const float*)d_in[0];
    const float* refpts  = (const float*)d_in[1];
    const float* fmaps   = (const float*)d_in[2];
    const float* W_off   = (const float*)d_in[4];
    const float* b_off   = (const float*)d_in[5];
    const float* W_attn  = (const float*)d_in[6];
    const float* b_attn  = (const float*)d_in[7];
    const float* W_out   = (const float*)d_in[8];
    const float* b_out   = (const float*)d_in[9];
    float* out = (float*)d_out;

    qproj_kernel<<<dim3(5, MROWS / 128), 256>>>(query, W_off, b_off,
                                                W_attn, b_attn, fmaps);
    sample_kernel<<<MROWS, 256>>>(refpts);
    outproj_kernel<<<dim3(2, MROWS / 128), 256>>>(W_out, b_out, out);
}

// round 11
// speedup vs baseline: 2.9435x; 1.0418x over previous
#include <cuda_runtime.h>
#include <cuda_fp16.h>
#include <cstdint>

// ---------------------------------------------------------------------------
// Problem constants
// ---------------------------------------------------------------------------
#define LQ      4096
#define NB      8
#define CDIM    256
#define MROWS   (LQ * NB)          // 32768
#define NHEADS  8
#define NLEV    4
#define NPTS    4
#define DH      32
#define FMSTRIDE (NB * CDIM)       // 2048 elems per spatial cell row
#define LTOTAL  13294
#define FMELEMS (LTOTAL * FMSTRIDE)   // 27,226,112

// ---------------------------------------------------------------------------
// Scratch (__device__ globals; cudaMalloc forbidden)
// ---------------------------------------------------------------------------
__device__ float  g_off[MROWS * 256];
__device__ float  g_logits[MROWS * 128];
__device__ float  g_agg[MROWS * 256];
__device__ __half g_fm16[FMELEMS];     // fp16 copy of feature maps (~54 MB)

// ---------------------------------------------------------------------------
// MMA / cp.async helpers
// ---------------------------------------------------------------------------
__device__ __forceinline__ void mma_tf32(float* c, const uint32_t* a, const uint32_t* b) {
    asm volatile(
        "mma.sync.aligned.m16n8k8.row.col.f32.tf32.tf32.f32 "
        "{%0,%1,%2,%3}, {%4,%5,%6,%7}, {%8,%9}, {%0,%1,%2,%3};"
        : "+f"(c[0]), "+f"(c[1]), "+f"(c[2]), "+f"(c[3])
        : "r"(a[0]), "r"(a[1]), "r"(a[2]), "r"(a[3]), "r"(b[0]), "r"(b[1]));
}

__device__ __forceinline__ void cp16(uint32_t saddr, const void* gptr) {
    asm volatile("cp.async.cg.shared.global [%0], [%1], 16;" :: "r"(saddr), "l"(gptr));
}
__device__ __forceinline__ void cp_commit() {
    asm volatile("cp.async.commit_group;");
}
__device__ __forceinline__ void cp_wait0() {
    asm volatile("cp.async.wait_group 0;");
}

// ---------------------------------------------------------------------------
// TF32 MMA GEMM core: 128x128 tile, BK=16, 256 threads (8 warps, 4x2 grid).
// Raw fp32 bits fed to tf32 MMA (HW truncates to tf32) -> no cvt ops.
// cp.async 2-stage staging, one __syncthreads per k-block.
// As[128][20]: stride 20 mod 32 -> fragment reads conflict-free.
// ---------------------------------------------------------------------------
__device__ __forceinline__ void mma_gemm_core(const float* __restrict__ Ab,
                                              const float* __restrict__ Bb,
                                              const float* __restrict__ biasp,
                                              float* __restrict__ Cb,
                                              int ldb, int ldc, int K) {
    __shared__ uint32_t As[2][128][20];
    __shared__ uint32_t Bs[2][16][136];

    const int tid  = threadIdx.x;
    const int wid  = tid >> 5;
    const int lane = tid & 31;
    const int gid  = lane >> 2;
    const int tig  = lane & 3;
    const int wm   = (wid & 3) * 32;
    const int wn   = (wid >> 2) * 64;

    // staging maps: A 128x16 (2x 16B per thread), B 16x128 (2x 16B per thread)
    const int arow = tid >> 1;
    const int acol = (tid & 1) * 8;
    const int brow = tid >> 5;
    const int bcol = (tid & 31) * 4;

    const uint32_t sA = (uint32_t)__cvta_generic_to_shared(&As[0][0][0]);
    const uint32_t sB = (uint32_t)__cvta_generic_to_shared(&Bs[0][0][0]);

    float acc[2][8][4];
#pragma unroll
    for (int i = 0; i < 2; i++)
#pragma unroll
        for (int j = 0; j < 8; j++)
#pragma unroll
            for (int v = 0; v < 4; v++) acc[i][j][v] = 0.f;

    const int nk = K / 16;

    // issue copies for stage st covering k0..k0+15
    auto issue_stage = [&](int st, int k0) {
        const uint32_t a0 = sA + (((st * 128 + arow) * 20) + acol) * 4;
        cp16(a0,      Ab + (size_t)arow * K + k0 + acol);
        cp16(a0 + 16, Ab + (size_t)arow * K + k0 + acol + 4);
        const uint32_t b0 = sB + (((st * 16 + brow) * 136) + bcol) * 4;
        cp16(b0,                Bb + (size_t)(k0 + brow) * ldb + bcol);
        cp16(b0 + 8 * 136 * 4,  Bb + (size_t)(k0 + brow + 8) * ldb + bcol);
    };

    issue_stage(0, 0);
    cp_commit();

    for (int kb = 0; kb < nk; kb++) {
        const int cur = kb & 1;
        cp_wait0();
        __syncthreads();
        if (kb + 1 < nk) {
            issue_stage(1 - cur, (kb + 1) * 16);
            cp_commit();
        }

#pragma unroll
        for (int ks = 0; ks < 2; ks++) {
            const int kk = ks * 8;
            uint32_t af[2][4];
#pragma unroll
            for (int mi = 0; mi < 2; mi++) {
                const int r = wm + mi * 16 + gid;
                af[mi][0] = As[cur][r][kk + tig];
                af[mi][1] = As[cur][r + 8][kk + tig];
                af[mi][2] = As[cur][r][kk + tig + 4];
                af[mi][3] = As[cur][r + 8][kk + tig + 4];
            }
            uint32_t bf[8][2];
#pragma unroll
            for (int ni = 0; ni < 8; ni++) {
                const int c = wn + ni * 8 + gid;
                bf[ni][0] = Bs[cur][kk + tig][c];
                bf[ni][1] = Bs[cur][kk + tig + 4][c];
            }
#pragma unroll
            for (int mi = 0; mi < 2; mi++)
#pragma unroll
                for (int ni = 0; ni < 8; ni++)
                    mma_tf32(acc[mi][ni], af[mi], bf[ni]);
        }
    }

#pragma unroll
    for (int mi = 0; mi < 2; mi++) {
        const int r = wm + mi * 16 + gid;
#pragma unroll
        for (int ni = 0; ni < 8; ni++) {
            const int c = wn + ni * 8 + tig * 2;
            const float bia0 = biasp[c], bia1 = biasp[c + 1];
            float2 lo = make_float2(acc[mi][ni][0] + bia0, acc[mi][ni][1] + bia1);
            float2 hi = make_float2(acc[mi][ni][2] + bia0, acc[mi][ni][3] + bia1);
            *(float2*)(Cb + (size_t)r * ldc + c)       = lo;
            *(float2*)(Cb + (size_t)(r + 8) * ldc + c) = hi;
        }
    }
}

// ---------------------------------------------------------------------------
// Fused Q-projection + fm->fp16 conversion.
// bx in {0,1}: W_off col tiles. bx==2: W_attn. bx in {3,4}: conversion blocks
// (512 total, grid-stride). DRAM-bound convert overlaps tensor-bound GEMM.
// ---------------------------------------------------------------------------
__global__ __launch_bounds__(256)
void qproj_kernel(const float* __restrict__ Q,
                  const float* __restrict__ Woff, const float* __restrict__ boff,
                  const float* __restrict__ Wattn, const float* __restrict__ battn,
                  const float* __restrict__ fm) {
    const int bx = blockIdx.x, by = blockIdx.y;
    if (bx < 2) {
        mma_gemm_core(Q + (size_t)by * 128 * 256, Woff + bx * 128, boff + bx * 128,
                      g_off + (size_t)by * 128 * 256 + bx * 128, 256, 256, 256);
    } else if (bx == 2) {
        mma_gemm_core(Q + (size_t)by * 128 * 256, Wattn, battn,
                      g_logits + (size_t)by * 128 * 128, 128, 128, 256);
    } else {
        const int cb = (bx - 3) * 256 + by;           // 0..511 conv block id
        const size_t nvec = FMELEMS / 4;
        for (size_t i = (size_t)cb * 256 + threadIdx.x; i < nvec; i += 512 * 256) {
            const float4 v = *(const float4*)(fm + i * 4);
            __half2 lo = __floats2half2_rn(v.x, v.y);
            __half2 hi = __floats2half2_rn(v.z, v.w);
            uint2 pk;
            pk.x = *(const uint32_t*)&lo;
            pk.y = *(const uint32_t*)&hi;
            *(uint2*)(g_fm16 + i * 4) = pk;
        }
    }
}

__global__ __launch_bounds__(256)
void outproj_kernel(const float* __restrict__ W, const float* __restrict__ bias,
                    float* __restrict__ out) {
    const int bx = blockIdx.x, by = blockIdx.y;
    mma_gemm_core(g_agg + (size_t)by * 128 * 256, W + bx * 128, bias + bx * 128,
                  out + (size_t)by * 128 * 256 + bx * 128, 256, 256, 256);
}

// ---------------------------------------------------------------------------
// Sampling, two-phase (at ~72% of L2 bandwidth cap).
// Phase 1 (threads 0..127): softmax + per-tap {clamped cell offset, weight
// with validity folded} -> 4KB smem.
// Phase 2 (8 warps = 8 heads): lane = (pt parity, tap, channel octet);
// inner loop: 2 LDS + 1 LDG.128 fp16 + 8 FMA.
// ---------------------------------------------------------------------------
__global__ __launch_bounds__(256)
void sample_kernel(const float* __restrict__ refpts) {
    __shared__ int   s_cell[NHEADS][16][4];
    __shared__ float s_w[NHEADS][16][4];

    const int r  = blockIdx.x;
    const int n  = r & (NB - 1);
    const int lq = r >> 3;

    const int tid = threadIdx.x;

    // ---- Phase 1 ----
    if (tid < 128) {
        const int h  = tid >> 4;
        const int pt = tid & 15;
        const int l  = pt >> 2;

        const int starts[4] = {0, 10000, 12500, 13125};
        const int dims[4]   = {100, 50, 25, 13};
        const int Wi = dims[l], Hi = dims[l];
        const float Wf = (float)Wi, Hf = (float)Hi;

        const float logit = g_logits[r * 128 + tid];
        float mx = logit;
#pragma unroll
        for (int sh = 8; sh > 0; sh >>= 1)
            mx = fmaxf(mx, __shfl_xor_sync(0xffffffffu, mx, sh));
        float ex = __expf(logit - mx);
        float sm = ex;
#pragma unroll
        for (int sh = 8; sh > 0; sh >>= 1)
            sm += __shfl_xor_sync(0xffffffffu, sm, sh);
        const float wgt = ex / sm;

        const float2 off = ((const float2*)g_off)[(size_t)r * 128 + tid];
        const float2 ref = ((const float2*)refpts)[(size_t)(n * LQ + lq) * NLEV + l];

        const float x = (ref.x + off.x / Wf) * Wf - 0.5f;
        const float y = (ref.y + off.y / Hf) * Hf - 0.5f;
        const float x0f = floorf(x), y0f = floorf(y);
        const int   x0 = (int)x0f,  y0 = (int)y0f;
        const float wx = x - x0f,   wy = y - y0f;

#pragma unroll
        for (int g = 0; g < 4; g++) {
            const int xi = x0 + (g & 1);
            const int yi = y0 + (g >> 1);
            const bool valid = (xi >= 0) & (xi < Wi) & (yi >= 0) & (yi < Hi);
            const int xc = min(max(xi, 0), Wi - 1);
            const int yc = min(max(yi, 0), Hi - 1);
            s_cell[h][pt][g] = (starts[l] + yc * Wi + xc) * FMSTRIDE;
            const float w = ((g & 1) ? wx : 1.f - wx)
                          * ((g >> 1) ? wy : 1.f - wy) * wgt;
            s_w[h][pt][g] = valid ? w : 0.f;
        }
    }
    __syncthreads();

    // ---- Phase 2 ----
    const int h    = tid >> 5;
    const int lane = tid & 31;
    const int q    = lane >> 4;
    const int g    = (lane >> 2) & 3;
    const int s    = lane & 3;

    const __half* gbase = g_fm16 + n * CDIM + h * DH + s * 8;

    float acc[8];
#pragma unroll
    for (int k = 0; k < 8; k++) acc[k] = 0.f;

#pragma unroll
    for (int t = 0; t < 8; t++) {
        const int pt = t * 2 + q;
        const int   cell = s_cell[h][pt][g];
        const float w    = s_w[h][pt][g];

        const uint4 raw = *(const uint4*)(gbase + cell);
        const float2 v0 = __half22float2(*(const __half2*)&raw.x);
        const float2 v1 = __half22float2(*(const __half2*)&raw.y);
        const float2 v2 = __half22float2(*(const __half2*)&raw.z);
        const float2 v3 = __half22float2(*(const __half2*)&raw.w);
        acc[0] = fmaf(v0.x, w, acc[0]); acc[1] = fmaf(v0.y, w, acc[1]);
        acc[2] = fmaf(v1.x, w, acc[2]); acc[3] = fmaf(v1.y, w, acc[3]);
        acc[4] = fmaf(v2.x, w, acc[4]); acc[5] = fmaf(v2.y, w, acc[5]);
        acc[6] = fmaf(v3.x, w, acc[6]); acc[7] = fmaf(v3.y, w, acc[7]);
    }

#pragma unroll
    for (int m = 4; m <= 16; m <<= 1) {
#pragma unroll
        for (int k = 0; k < 8; k++)
            acc[k] += __shfl_xor_sync(0xffffffffu, acc[k], m);
    }

    if (lane < 4) {
        float* dst = g_agg + (size_t)r * 256 + h * 32 + s * 8;
        *(float4*)(dst)     = make_float4(acc[0], acc[1], acc[2], acc[3]);
        *(float4*)(dst + 4) = make_float4(acc[4], acc[5], acc[6], acc[7]);
    }
}

// ---------------------------------------------------------------------------
// Launch
// ---------------------------------------------------------------------------
extern "C" void kernel_launch(void* const* d_in, const int* in_sizes, int n_in,
                              void* d_out, int out_size) {
    const float* query   = (const float*)d_in[0];
    const float* refpts  = (const float*)d_in[1];
    const float* fmaps   = (const float*)d_in[2];
    const float* W_off   = (const float*)d_in[4];
    const float* b_off   = (const float*)d_in[5];
    const float* W_attn  = (const float*)d_in[6];
    const float* b_attn  = (const float*)d_in[7];
    const float* W_out   = (const float*)d_in[8];
    const float* b_out   = (const float*)d_in[9];
    float* out = (float*)d_out;

    qproj_kernel<<<dim3(5, MROWS / 128), 256>>>(query, W_off, b_off,
                                                W_attn, b_attn, fmaps);
    sample_kernel<<<MROWS, 256>>>(refpts);
    outproj_kernel<<<dim3(2, MROWS / 128), 256>>>(W_out, b_out, out);
}